// round 1
// baseline (speedup 1.0000x reference)
#include <cuda_runtime.h>
#include <cuda_bf16.h>
#include <cstdint>

// Fixed problem shape: N = M = 8192, D = 128, fp32 in/out.
#define DMAX 128
#define NMAX 8192

// Scratch (device globals — no allocation allowed in kernel_launch)
__device__ __align__(16) __nv_bfloat16 g_Abf[NMAX * DMAX];
__device__ __align__(16) __nv_bfloat16 g_Bbf[NMAX * DMAX];
__device__ float g_a2[NMAX];
__device__ float g_b2[NMAX];

// ---------------------------------------------------------------------------
// Prep: convert one row (128 floats) to bf16 and compute exact fp32 sum(x^2).
// One block (128 threads) per row.
// ---------------------------------------------------------------------------
__global__ void prep_kernel(const float* __restrict__ src, int which) {
    const int row = blockIdx.x;
    const int t = threadIdx.x;            // 0..127
    float v = src[row * DMAX + t];
    __nv_bfloat16 bv = __float2bfloat16(v);
    if (which == 0) g_Abf[row * DMAX + t] = bv;
    else            g_Bbf[row * DMAX + t] = bv;

    float s = v * v;
    #pragma unroll
    for (int off = 16; off > 0; off >>= 1)
        s += __shfl_xor_sync(0xFFFFFFFFu, s, off);

    __shared__ float ps[4];
    if ((t & 31) == 0) ps[t >> 5] = s;
    __syncthreads();
    if (t == 0) {
        float tot = ps[0] + ps[1] + ps[2] + ps[3];
        if (which == 0) g_a2[row] = tot;
        else            g_b2[row] = tot;
    }
}

// ---------------------------------------------------------------------------
// GEMM + fused distance epilogue.
// CTA tile 128x128, K chunked 2x64, 256 threads (8 warps, 4x2 warp grid),
// warp tile 32x64, mma.sync m16n8k16 bf16 -> fp32.
// ---------------------------------------------------------------------------
#define BK 64
#define LDS_PAD 8
#define LDT (BK + LDS_PAD)   // 72 bf16 per smem row (144 B stride: conflict-free ldmatrix)

__device__ __forceinline__ unsigned smem_u32(const void* p) {
    return (unsigned)__cvta_generic_to_shared(p);
}

__device__ __forceinline__ void ldsm_x4(unsigned r[4], unsigned addr) {
    asm volatile("ldmatrix.sync.aligned.m8n8.x4.shared.b16 {%0,%1,%2,%3}, [%4];"
                 : "=r"(r[0]), "=r"(r[1]), "=r"(r[2]), "=r"(r[3]) : "r"(addr));
}

__device__ __forceinline__ void mma16816(float c[4], const unsigned a[4], const unsigned b0, const unsigned b1) {
    asm volatile(
        "mma.sync.aligned.m16n8k16.row.col.f32.bf16.bf16.f32 "
        "{%0,%1,%2,%3}, {%4,%5,%6,%7}, {%8,%9}, {%0,%1,%2,%3};"
        : "+f"(c[0]), "+f"(c[1]), "+f"(c[2]), "+f"(c[3])
        : "r"(a[0]), "r"(a[1]), "r"(a[2]), "r"(a[3]), "r"(b0), "r"(b1));
}

__device__ __forceinline__ float neg_sqrt(float d2) {
    if (d2 <= 0.0f) return 0.0f;
    float r;
    asm("rsqrt.approx.f32 %0, %1;" : "=f"(r) : "f"(d2));
    return -(d2 * r);     // -sqrt(d2), rel err ~2^-22
}

__global__ __launch_bounds__(256, 2)
void dist_gemm_kernel(float* __restrict__ out, int M) {
    __shared__ __nv_bfloat16 As[128][LDT];
    __shared__ __nv_bfloat16 Bs[128][LDT];
    __shared__ float a2s[128];
    __shared__ float b2s[128];

    const int tid  = threadIdx.x;
    const int lane = tid & 31;
    const int wid  = tid >> 5;          // 0..7
    const int wr   = wid & 3;           // warp row (x32)
    const int wc   = wid >> 2;          // warp col (x64)

    const int rowBase = blockIdx.y * 128;
    const int colBase = blockIdx.x * 128;

    if (tid < 128)        a2s[tid]        = g_a2[rowBase + tid];
    else                  b2s[tid - 128]  = g_b2[colBase + (tid - 128)];

    float acc[2][8][4];
    #pragma unroll
    for (int i = 0; i < 2; i++)
        #pragma unroll
        for (int j = 0; j < 8; j++)
            #pragma unroll
            for (int k = 0; k < 4; k++)
                acc[i][j][k] = 0.0f;

    // gmem tile pointers (uint4 = 8 bf16); row stride = 128 bf16 = 16 uint4
    const uint4* gA = reinterpret_cast<const uint4*>(g_Abf) + (size_t)rowBase * 16;
    const uint4* gB = reinterpret_cast<const uint4*>(g_Bbf) + (size_t)colBase * 16;

    #pragma unroll
    for (int chunk = 0; chunk < 2; chunk++) {
        // ---- load 128x64 bf16 tiles (8 uint4 per row) ----
        {
            const int c = tid & 7;          // uint4 col 0..7 within chunk
            const int r0 = tid >> 3;        // 0..31
            #pragma unroll
            for (int p = 0; p < 4; p++) {
                const int r = p * 32 + r0;
                uint4 va = gA[(size_t)r * 16 + chunk * 8 + c];
                uint4 vb = gB[(size_t)r * 16 + chunk * 8 + c];
                *reinterpret_cast<uint4*>(&As[r][c * 8]) = va;
                *reinterpret_cast<uint4*>(&Bs[r][c * 8]) = vb;
            }
        }
        __syncthreads();

        // ---- compute 4 k-steps of 16 ----
        #pragma unroll
        for (int kk = 0; kk < 4; kk++) {
            unsigned afrag[2][4];
            #pragma unroll
            for (int mt = 0; mt < 2; mt++) {
                unsigned addr = smem_u32(
                    &As[wr * 32 + mt * 16 + (lane & 15)][kk * 16 + (lane >> 4) * 8]);
                ldsm_x4(afrag[mt], addr);
            }
            unsigned bfrag[4][4];   // 4 pairs of n-tiles, each x4 covers 2 n-tiles
            #pragma unroll
            for (int np = 0; np < 4; np++) {
                unsigned addr = smem_u32(
                    &Bs[wc * 64 + np * 16 + (lane & 7) + ((lane >> 4) * 8)]
                       [kk * 16 + ((lane >> 3) & 1) * 8]);
                ldsm_x4(bfrag[np], addr);
            }
            #pragma unroll
            for (int mt = 0; mt < 2; mt++)
                #pragma unroll
                for (int np = 0; np < 4; np++) {
                    mma16816(acc[mt][np * 2 + 0], afrag[mt], bfrag[np][0], bfrag[np][1]);
                    mma16816(acc[mt][np * 2 + 1], afrag[mt], bfrag[np][2], bfrag[np][3]);
                }
        }
        __syncthreads();
    }

    // ---- epilogue: -sqrt(max(a2 + b2 - 2ab, 0)), float2 stores ----
    const int g = lane >> 2;            // group id 0..7
    const int cq = (lane & 3) * 2;      // col pair within n-tile
    #pragma unroll
    for (int mt = 0; mt < 2; mt++) {
        const int lr0 = wr * 32 + mt * 16 + g;
        const float a20 = a2s[lr0];
        const float a21 = a2s[lr0 + 8];
        const long long grow0 = rowBase + lr0;
        #pragma unroll
        for (int nt = 0; nt < 8; nt++) {
            const int lc = wc * 64 + nt * 8 + cq;
            const float b20 = b2s[lc];
            const float b21 = b2s[lc + 1];
            const int gcol = colBase + lc;

            float d00 = fmaf(-2.0f, acc[mt][nt][0], a20 + b20);
            float d01 = fmaf(-2.0f, acc[mt][nt][1], a20 + b21);
            float d10 = fmaf(-2.0f, acc[mt][nt][2], a21 + b20);
            float d11 = fmaf(-2.0f, acc[mt][nt][3], a21 + b21);

            float2 v0 = make_float2(neg_sqrt(d00), neg_sqrt(d01));
            float2 v1 = make_float2(neg_sqrt(d10), neg_sqrt(d11));

            *reinterpret_cast<float2*>(out + grow0 * M + gcol)       = v0;
            *reinterpret_cast<float2*>(out + (grow0 + 8) * M + gcol) = v1;
        }
    }
}

// ---------------------------------------------------------------------------
extern "C" void kernel_launch(void* const* d_in, const int* in_sizes, int n_in,
                              void* d_out, int out_size) {
    const float* zA = (const float*)d_in[0];   // z_anc     [N, 128]
    const float* zB = (const float*)d_in[1];   // z_pos_neg [M, 128]
    const int N = in_sizes[0] / DMAX;
    const int M = in_sizes[1] / DMAX;

    prep_kernel<<<N, 128>>>(zA, 0);
    prep_kernel<<<M, 128>>>(zB, 1);

    dim3 grid(M / 128, N / 128);
    dist_gemm_kernel<<<grid, 256>>>((float*)d_out, M);
}

// round 2
// speedup vs baseline: 1.1368x; 1.1368x over previous
#include <cuda_runtime.h>
#include <cuda_bf16.h>
#include <cstdint>

// Fixed problem shape: N = M = 8192, D = 128, fp32 in/out.
#define DMAX 128
#define NMAX 8192

// Scratch (device globals — no allocation allowed in kernel_launch)
__device__ __align__(16) __nv_bfloat16 g_Abf[NMAX * DMAX];
__device__ __align__(16) __nv_bfloat16 g_Bbf[NMAX * DMAX];
__device__ float g_a2[NMAX];
__device__ float g_b2[NMAX];

// ---------------------------------------------------------------------------
// Fused prep: one WARP per row across both matrices.
// Each lane: float4 load (4 elems), bf16 convert + packed store, fp32 sum(x^2).
// ---------------------------------------------------------------------------
__global__ void prep_fused(const float* __restrict__ A, const float* __restrict__ B,
                           int N, int M) {
    const int warp = (blockIdx.x * blockDim.x + threadIdx.x) >> 5;
    const int lane = threadIdx.x & 31;
    if (warp >= N + M) return;

    const bool isA = warp < N;
    const int row = isA ? warp : warp - N;
    const float* src = (isA ? A : B) + (size_t)row * DMAX;

    float4 v = reinterpret_cast<const float4*>(src)[lane];

    __nv_bfloat162 lo = __floats2bfloat162_rn(v.x, v.y);
    __nv_bfloat162 hi = __floats2bfloat162_rn(v.z, v.w);
    uint2 packed = make_uint2(*reinterpret_cast<unsigned*>(&lo),
                              *reinterpret_cast<unsigned*>(&hi));
    __nv_bfloat16* dst = (isA ? g_Abf : g_Bbf) + (size_t)row * DMAX;
    reinterpret_cast<uint2*>(dst)[lane] = packed;

    float s = fmaf(v.x, v.x, fmaf(v.y, v.y, fmaf(v.z, v.z, v.w * v.w)));
    #pragma unroll
    for (int off = 16; off > 0; off >>= 1)
        s += __shfl_xor_sync(0xFFFFFFFFu, s, off);
    if (lane == 0) {
        if (isA) g_a2[row] = s;
        else     g_b2[row] = s;
    }
}

// ---------------------------------------------------------------------------
// GEMM + fused distance epilogue.
// CTA tile 128x128, full K=128 slab loaded once via cp.async, 256 threads
// (8 warps, 4x2 warp grid), warp tile 32x64, mma.sync m16n8k16 bf16 -> fp32.
// ---------------------------------------------------------------------------
#define LDT 136   // bf16 per smem row: 272B stride, row-to-row bank offset 4 -> conflict-free

__device__ __forceinline__ unsigned smem_u32(const void* p) {
    return (unsigned)__cvta_generic_to_shared(p);
}

__device__ __forceinline__ void cp_async16(void* smem, const void* gmem) {
    asm volatile("cp.async.cg.shared.global [%0], [%1], 16;"
                 :: "r"(smem_u32(smem)), "l"(gmem));
}

__device__ __forceinline__ void ldsm_x4(unsigned r[4], unsigned addr) {
    asm volatile("ldmatrix.sync.aligned.m8n8.x4.shared.b16 {%0,%1,%2,%3}, [%4];"
                 : "=r"(r[0]), "=r"(r[1]), "=r"(r[2]), "=r"(r[3]) : "r"(addr));
}

__device__ __forceinline__ void mma16816(float c[4], const unsigned a[4],
                                         const unsigned b0, const unsigned b1) {
    asm volatile(
        "mma.sync.aligned.m16n8k16.row.col.f32.bf16.bf16.f32 "
        "{%0,%1,%2,%3}, {%4,%5,%6,%7}, {%8,%9}, {%0,%1,%2,%3};"
        : "+f"(c[0]), "+f"(c[1]), "+f"(c[2]), "+f"(c[3])
        : "r"(a[0]), "r"(a[1]), "r"(a[2]), "r"(a[3]), "r"(b0), "r"(b1));
}

__device__ __forceinline__ float neg_sqrt(float d2) {
    if (d2 <= 0.0f) return 0.0f;
    float r;
    asm("rsqrt.approx.f32 %0, %1;" : "=f"(r) : "f"(d2));
    return -(d2 * r);     // -sqrt(d2)
}

#define SMEM_BYTES (2 * 128 * LDT * 2 + 256 * 4)

__global__ __launch_bounds__(256, 2)
void dist_gemm_kernel(float* __restrict__ out, int M) {
    extern __shared__ char smem_raw[];
    __nv_bfloat16 (*As)[LDT] = reinterpret_cast<__nv_bfloat16(*)[LDT]>(smem_raw);
    __nv_bfloat16 (*Bs)[LDT] = reinterpret_cast<__nv_bfloat16(*)[LDT]>(smem_raw + 128 * LDT * 2);
    float* a2s = reinterpret_cast<float*>(smem_raw + 2 * 128 * LDT * 2);
    float* b2s = a2s + 128;

    const int tid  = threadIdx.x;
    const int lane = tid & 31;
    const int wid  = tid >> 5;          // 0..7
    const int wr   = wid & 3;           // warp row (x32)
    const int wc   = wid >> 2;          // warp col (x64)

    const int rowBase = blockIdx.y * 128;
    const int colBase = blockIdx.x * 128;

    // ---- async load full 128x128 bf16 tiles (16 uint4 per row) ----
    {
        const int c  = tid & 15;        // uint4 col 0..15
        const int r0 = tid >> 4;        // 0..15
        const uint4* gA = reinterpret_cast<const uint4*>(g_Abf) + (size_t)rowBase * 16;
        const uint4* gB = reinterpret_cast<const uint4*>(g_Bbf) + (size_t)colBase * 16;
        #pragma unroll
        for (int p = 0; p < 8; p++) {
            const int r = p * 16 + r0;
            cp_async16(&As[r][c * 8], &gA[(size_t)r * 16 + c]);
            cp_async16(&Bs[r][c * 8], &gB[(size_t)r * 16 + c]);
        }
        asm volatile("cp.async.commit_group;");
    }

    if (tid < 128)       a2s[tid]       = g_a2[rowBase + tid];
    else                 b2s[tid - 128] = g_b2[colBase + (tid - 128)];

    float acc[2][8][4];
    #pragma unroll
    for (int i = 0; i < 2; i++)
        #pragma unroll
        for (int j = 0; j < 8; j++)
            #pragma unroll
            for (int k = 0; k < 4; k++)
                acc[i][j][k] = 0.0f;

    asm volatile("cp.async.wait_group 0;");
    __syncthreads();

    // ---- compute 8 k-steps of 16 ----
    #pragma unroll
    for (int kk = 0; kk < 8; kk++) {
        unsigned afrag[2][4];
        #pragma unroll
        for (int mt = 0; mt < 2; mt++) {
            unsigned addr = smem_u32(
                &As[wr * 32 + mt * 16 + (lane & 15)][kk * 16 + (lane >> 4) * 8]);
            ldsm_x4(afrag[mt], addr);
        }
        unsigned bfrag[4][4];   // 4 pairs of n-tiles, each x4 covers 2 n-tiles
        #pragma unroll
        for (int np = 0; np < 4; np++) {
            unsigned addr = smem_u32(
                &Bs[wc * 64 + np * 16 + (lane & 7) + ((lane >> 4) * 8)]
                   [kk * 16 + ((lane >> 3) & 1) * 8]);
            ldsm_x4(bfrag[np], addr);
        }
        #pragma unroll
        for (int mt = 0; mt < 2; mt++)
            #pragma unroll
            for (int np = 0; np < 4; np++) {
                mma16816(acc[mt][np * 2 + 0], afrag[mt], bfrag[np][0], bfrag[np][1]);
                mma16816(acc[mt][np * 2 + 1], afrag[mt], bfrag[np][2], bfrag[np][3]);
            }
    }

    // ---- epilogue: -sqrt(max(a2 + b2 - 2ab, 0)), float2 stores ----
    const int g  = lane >> 2;           // group id 0..7
    const int cq = (lane & 3) * 2;      // col pair within n-tile
    #pragma unroll
    for (int mt = 0; mt < 2; mt++) {
        const int lr0 = wr * 32 + mt * 16 + g;
        const float a20 = a2s[lr0];
        const float a21 = a2s[lr0 + 8];
        const long long grow0 = rowBase + lr0;
        #pragma unroll
        for (int nt = 0; nt < 8; nt++) {
            const int lc = wc * 64 + nt * 8 + cq;
            const float b20 = b2s[lc];
            const float b21 = b2s[lc + 1];
            const int gcol = colBase + lc;

            float d00 = fmaf(-2.0f, acc[mt][nt][0], a20 + b20);
            float d01 = fmaf(-2.0f, acc[mt][nt][1], a20 + b21);
            float d10 = fmaf(-2.0f, acc[mt][nt][2], a21 + b20);
            float d11 = fmaf(-2.0f, acc[mt][nt][3], a21 + b21);

            float2 v0 = make_float2(neg_sqrt(d00), neg_sqrt(d01));
            float2 v1 = make_float2(neg_sqrt(d10), neg_sqrt(d11));

            *reinterpret_cast<float2*>(out + grow0 * M + gcol)       = v0;
            *reinterpret_cast<float2*>(out + (grow0 + 8) * M + gcol) = v1;
        }
    }
}

// ---------------------------------------------------------------------------
extern "C" void kernel_launch(void* const* d_in, const int* in_sizes, int n_in,
                              void* d_out, int out_size) {
    const float* zA = (const float*)d_in[0];   // z_anc     [N, 128]
    const float* zB = (const float*)d_in[1];   // z_pos_neg [M, 128]
    const int N = in_sizes[0] / DMAX;
    const int M = in_sizes[1] / DMAX;

    cudaFuncSetAttribute(dist_gemm_kernel,
                         cudaFuncAttributeMaxDynamicSharedMemorySize, SMEM_BYTES);

    const int totalWarps = N + M;
    prep_fused<<<(totalWarps * 32 + 255) / 256, 256>>>(zA, zB, N, M);

    dim3 grid(M / 128, N / 128);
    dist_gemm_kernel<<<grid, 256, SMEM_BYTES>>>((float*)d_out, M);
}